// round 16
// baseline (speedup 1.0000x reference)
#include <cuda_runtime.h>
#include <cuda_fp16.h>
#include <cstdint>

// CycleEmbedding via code-count factorization:
//   out[c,:] = sum_k count[c,k] * emb[k,:]
// x: [100000] int32 (0..21), atom_to_cycle: [2, 600000] int32,
// emb_weight: [22,128] f32, out: [100000,128] f32.
//
// g_counts zero-initialized at module load; expand_kernel restores every entry
// it reads to zero, preserving the all-zero invariant across graph replays.
//
// Expand: fp16 emb in smem, transposed term lists (broadcast LDS.128), and
// per-warp descending slot sort + tiered loops to cut padded row-slots.

#define HIDDEN 128
#define NUM_CODES 22
#define MAX_SEGMENTS 100000
#define ROWS_PER_WARP 4
#define EWARPS 16
#define ETHREADS (EWARPS * 32)                    // 512
#define ROWS_PER_BLOCK (EWARPS * ROWS_PER_WARP)   // 64

__device__ int g_counts[MAX_SEGMENTS * NUM_CODES];   // 8.8 MB scratch, zero-init

__global__ void __launch_bounds__(256) count_kernel(
    const int* __restrict__ x,
    const int* __restrict__ atom_idx,
    const int* __restrict__ cycle_idx,
    int E8)
{
    int g = blockIdx.x * blockDim.x + threadIdx.x;
    if (g >= E8) return;

    const int4* a4 = reinterpret_cast<const int4*>(atom_idx) + g * 2;
    const int4* c4 = reinterpret_cast<const int4*>(cycle_idx) + g * 2;
    int4 a0 = __ldg(a4);     int4 a1 = __ldg(a4 + 1);
    int4 c0 = __ldg(c4);     int4 c1 = __ldg(c4 + 1);

    int k0 = __ldg(&x[a0.x]); int k1 = __ldg(&x[a0.y]);
    int k2 = __ldg(&x[a0.z]); int k3 = __ldg(&x[a0.w]);
    int k4 = __ldg(&x[a1.x]); int k5 = __ldg(&x[a1.y]);
    int k6 = __ldg(&x[a1.z]); int k7 = __ldg(&x[a1.w]);

    atomicAdd(&g_counts[c0.x * NUM_CODES + k0], 1);
    atomicAdd(&g_counts[c0.y * NUM_CODES + k1], 1);
    atomicAdd(&g_counts[c0.z * NUM_CODES + k2], 1);
    atomicAdd(&g_counts[c0.w * NUM_CODES + k3], 1);
    atomicAdd(&g_counts[c1.x * NUM_CODES + k4], 1);
    atomicAdd(&g_counts[c1.y * NUM_CODES + k5], 1);
    atomicAdd(&g_counts[c1.z * NUM_CODES + k6], 1);
    atomicAdd(&g_counts[c1.w * NUM_CODES + k7], 1);
}

__global__ void __launch_bounds__(256) count_tail_kernel(
    const int* __restrict__ x,
    const int* __restrict__ atom_idx,
    const int* __restrict__ cycle_idx,
    int start, int E)
{
    int e = start + blockIdx.x * blockDim.x + threadIdx.x;
    if (e >= E) return;
    int a = __ldg(&atom_idx[e]);
    int c = __ldg(&cycle_idx[e]);
    int code = __ldg(&x[a]);
    atomicAdd(&g_counts[c * NUM_CODES + code], 1);
}

__global__ void __launch_bounds__(ETHREADS, 3) expand_kernel(
    const float* __restrict__ emb,       // [22, 128]
    float* __restrict__ out,             // [S, 128]
    int S)
{
    __shared__ __half2 s_emb[NUM_CODES * HIDDEN / 2];     // 5.5 KB, fp16
    __shared__ int4    s_term4[EWARPS * NUM_CODES];       // 5.6 KB

    // stage emb -> fp16 smem
    {
        const float4* e4 = reinterpret_cast<const float4*>(emb);
        for (int i = threadIdx.x; i < NUM_CODES * HIDDEN / 4; i += ETHREADS) {
            float4 v = __ldg(e4 + i);
            s_emb[i * 2 + 0] = __floats2half2_rn(v.x, v.y);
            s_emb[i * 2 + 1] = __floats2half2_rn(v.z, v.w);
        }
    }

    const int lane = threadIdx.x & 31;
    const int warp = threadIdx.x >> 5;                    // 0..15
    const int row_base = blockIdx.x * ROWS_PER_BLOCK + warp * ROWS_PER_WARP;
    const unsigned FULL = 0xffffffffu;

    // ---- load counts for 4 rows (independent 88B loads) ----
    int cnt[ROWS_PER_WARP];
    #pragma unroll
    for (int r = 0; r < ROWS_PER_WARP; r++) {
        int row = row_base + r;
        cnt[r] = (lane < NUM_CODES && row < S)
                   ? __ldg(&g_counts[row * NUM_CODES + lane]) : 0;
    }

    // ---- build packed term lists in registers ----
    // pack_r = ((code*256) << 16) | bf16bits((float)count)
    int pkv[ROWS_PER_WARP];
    int ntv[ROWS_PER_WARP];
    int rid[ROWS_PER_WARP];
    #pragma unroll
    for (int r = 0; r < ROWS_PER_WARP; r++) {
        unsigned mask = __ballot_sync(FULL, cnt[r] != 0);
        ntv[r] = __popc(mask);
        int code = (lane < ntv[r]) ? (__fns(mask, 0, lane + 1)) : 0;
        int c2 = __shfl_sync(FULL, cnt[r], code);
        unsigned bf = __float_as_uint((float)c2) >> 16;   // exact for small ints
        pkv[r] = (lane < ntv[r]) ? (((code * (HIDDEN * 2)) << 16) | (int)bf) : 0;
        rid[r] = row_base + r;
        // zero-restore
        if (lane < NUM_CODES && rid[r] < S)
            g_counts[rid[r] * NUM_CODES + lane] = 0;
    }

    // ---- sort the 4 slots by nt descending (warp-uniform conditions) ----
    #define CE(a, b) do { if (ntv[a] < ntv[b]) {                  \
        int t_ = ntv[a]; ntv[a] = ntv[b]; ntv[b] = t_;            \
        t_ = pkv[a]; pkv[a] = pkv[b]; pkv[b] = t_;                \
        t_ = rid[a]; rid[a] = rid[b]; rid[b] = t_; } } while (0)
    CE(0, 1); CE(2, 3); CE(0, 2); CE(1, 3); CE(1, 2);
    #undef CE

    if (lane < NUM_CODES)
        s_term4[warp * NUM_CODES + lane] = make_int4(pkv[0], pkv[1], pkv[2], pkv[3]);
    __syncwarp();
    __syncthreads();   // s_emb + s_term4 ready

    // ---- hot loops: tiered by sorted nt (nt0 >= nt1 >= nt2 >= nt3) ----
    const char* const embb = (const char*)s_emb;
    const uint32_t lane_off = (uint32_t)lane << 3;        // lane*8 bytes
    const int4* tlist = &s_term4[warp * NUM_CODES];

    float4 acc0 = make_float4(0.f,0.f,0.f,0.f), acc1 = acc0, acc2 = acc0, acc3 = acc0;

    int j = 0;
    for (; j < ntv[3]; j++) {                             // all 4 rows active
        int4 t = tlist[j];
        float f0 = __uint_as_float((unsigned)t.x << 16);
        float f1 = __uint_as_float((unsigned)t.y << 16);
        float f2 = __uint_as_float((unsigned)t.z << 16);
        float f3 = __uint_as_float((unsigned)t.w << 16);
        const __half2* p0 = reinterpret_cast<const __half2*>(embb + ((uint32_t)t.x >> 16) + lane_off);
        const __half2* p1 = reinterpret_cast<const __half2*>(embb + ((uint32_t)t.y >> 16) + lane_off);
        const __half2* p2 = reinterpret_cast<const __half2*>(embb + ((uint32_t)t.z >> 16) + lane_off);
        const __half2* p3 = reinterpret_cast<const __half2*>(embb + ((uint32_t)t.w >> 16) + lane_off);
        float2 a0 = __half22float2(p0[0]), b0 = __half22float2(p0[1]);
        float2 a1 = __half22float2(p1[0]), b1 = __half22float2(p1[1]);
        float2 a2 = __half22float2(p2[0]), b2 = __half22float2(p2[1]);
        float2 a3 = __half22float2(p3[0]), b3 = __half22float2(p3[1]);
        acc0.x += f0*a0.x; acc0.y += f0*a0.y; acc0.z += f0*b0.x; acc0.w += f0*b0.y;
        acc1.x += f1*a1.x; acc1.y += f1*a1.y; acc1.z += f1*b1.x; acc1.w += f1*b1.y;
        acc2.x += f2*a2.x; acc2.y += f2*a2.y; acc2.z += f2*b2.x; acc2.w += f2*b2.y;
        acc3.x += f3*a3.x; acc3.y += f3*a3.y; acc3.z += f3*b3.x; acc3.w += f3*b3.y;
    }
    for (; j < ntv[2]; j++) {                             // rows 0..2
        int4 t = tlist[j];
        float f0 = __uint_as_float((unsigned)t.x << 16);
        float f1 = __uint_as_float((unsigned)t.y << 16);
        float f2 = __uint_as_float((unsigned)t.z << 16);
        const __half2* p0 = reinterpret_cast<const __half2*>(embb + ((uint32_t)t.x >> 16) + lane_off);
        const __half2* p1 = reinterpret_cast<const __half2*>(embb + ((uint32_t)t.y >> 16) + lane_off);
        const __half2* p2 = reinterpret_cast<const __half2*>(embb + ((uint32_t)t.z >> 16) + lane_off);
        float2 a0 = __half22float2(p0[0]), b0 = __half22float2(p0[1]);
        float2 a1 = __half22float2(p1[0]), b1 = __half22float2(p1[1]);
        float2 a2 = __half22float2(p2[0]), b2 = __half22float2(p2[1]);
        acc0.x += f0*a0.x; acc0.y += f0*a0.y; acc0.z += f0*b0.x; acc0.w += f0*b0.y;
        acc1.x += f1*a1.x; acc1.y += f1*a1.y; acc1.z += f1*b1.x; acc1.w += f1*b1.y;
        acc2.x += f2*a2.x; acc2.y += f2*a2.y; acc2.z += f2*b2.x; acc2.w += f2*b2.y;
    }
    for (; j < ntv[1]; j++) {                             // rows 0..1
        int4 t = tlist[j];
        float f0 = __uint_as_float((unsigned)t.x << 16);
        float f1 = __uint_as_float((unsigned)t.y << 16);
        const __half2* p0 = reinterpret_cast<const __half2*>(embb + ((uint32_t)t.x >> 16) + lane_off);
        const __half2* p1 = reinterpret_cast<const __half2*>(embb + ((uint32_t)t.y >> 16) + lane_off);
        float2 a0 = __half22float2(p0[0]), b0 = __half22float2(p0[1]);
        float2 a1 = __half22float2(p1[0]), b1 = __half22float2(p1[1]);
        acc0.x += f0*a0.x; acc0.y += f0*a0.y; acc0.z += f0*b0.x; acc0.w += f0*b0.y;
        acc1.x += f1*a1.x; acc1.y += f1*a1.y; acc1.z += f1*b1.x; acc1.w += f1*b1.y;
    }
    for (; j < ntv[0]; j++) {                             // row 0 only
        int4 t = tlist[j];
        float f0 = __uint_as_float((unsigned)t.x << 16);
        const __half2* p0 = reinterpret_cast<const __half2*>(embb + ((uint32_t)t.x >> 16) + lane_off);
        float2 a0 = __half22float2(p0[0]), b0 = __half22float2(p0[1]);
        acc0.x += f0*a0.x; acc0.y += f0*a0.y; acc0.z += f0*b0.x; acc0.w += f0*b0.y;
    }

    float4* out4 = reinterpret_cast<float4*>(out);
    if (rid[0] < S) out4[(size_t)rid[0] * 32 + lane] = acc0;
    if (rid[1] < S) out4[(size_t)rid[1] * 32 + lane] = acc1;
    if (rid[2] < S) out4[(size_t)rid[2] * 32 + lane] = acc2;
    if (rid[3] < S) out4[(size_t)rid[3] * 32 + lane] = acc3;
}

extern "C" void kernel_launch(void* const* d_in, const int* in_sizes, int n_in,
                              void* d_out, int out_size)
{
    const int*   x   = (const int*)d_in[0];
    const int*   a2c = (const int*)d_in[1];
    const float* emb = (const float*)d_in[2];
    float*       out = (float*)d_out;

    const int E = in_sizes[1] / 2;                   // 600000
    const int S = out_size / HIDDEN;                 // 100000
    const int* atom_idx  = a2c;
    const int* cycle_idx = a2c + E;

    // 1) histogram edges into (cycle, code) counts, 8 edges/thread
    int E8 = E >> 3;
    if (E8 > 0)
        count_kernel<<<(E8 + 255) / 256, 256>>>(x, atom_idx, cycle_idx, E8);
    if (E & 7) {
        int start = E8 << 3, n = E - start;
        count_tail_kernel<<<(n + 255) / 256, 256>>>(x, atom_idx, cycle_idx, start, E);
    }

    // 2) expand counts -> output rows (64 rows/block); also re-zeros counts
    expand_kernel<<<(S + ROWS_PER_BLOCK - 1) / ROWS_PER_BLOCK, ETHREADS>>>(emb, out, S);
}

// round 17
// speedup vs baseline: 1.0727x; 1.0727x over previous
#include <cuda_runtime.h>
#include <cuda_fp16.h>
#include <cstdint>

// CycleEmbedding via code-count factorization:
//   out[c,:] = sum_k count[c,k] * emb[k,:]
// x: [100000] int32 (0..21), atom_to_cycle: [2, 600000] int32,
// emb_weight: [22,128] f32, out: [100000,128] f32.
//
// g_counts zero-initialized at module load; expand_kernel restores every entry
// it reads to zero, preserving the all-zero invariant across graph replays.
//
// Expand: fp16 emb in smem (halved LDS bytes), transposed term lists
// (broadcast LDS.128 replaces 4 SHFLs), single 4-row interleaved hot loop,
// 512-thread blocks to amortize emb staging.

#define HIDDEN 128
#define NUM_CODES 22
#define MAX_SEGMENTS 100000
#define ROWS_PER_WARP 4
#define EWARPS 16
#define ETHREADS (EWARPS * 32)                    // 512
#define ROWS_PER_BLOCK (EWARPS * ROWS_PER_WARP)   // 64

__device__ int g_counts[MAX_SEGMENTS * NUM_CODES];   // 8.8 MB scratch, zero-init

__global__ void __launch_bounds__(256) count_kernel(
    const int* __restrict__ x,
    const int* __restrict__ atom_idx,
    const int* __restrict__ cycle_idx,
    int E4)                                 // number of 4-edge groups
{
    int g = blockIdx.x * blockDim.x + threadIdx.x;
    if (g >= E4) return;

    int4 a = __ldg(reinterpret_cast<const int4*>(atom_idx) + g);
    int4 c = __ldg(reinterpret_cast<const int4*>(cycle_idx) + g);

    int k0 = __ldg(&x[a.x]);
    int k1 = __ldg(&x[a.y]);
    int k2 = __ldg(&x[a.z]);
    int k3 = __ldg(&x[a.w]);

    atomicAdd(&g_counts[c.x * NUM_CODES + k0], 1);
    atomicAdd(&g_counts[c.y * NUM_CODES + k1], 1);
    atomicAdd(&g_counts[c.z * NUM_CODES + k2], 1);
    atomicAdd(&g_counts[c.w * NUM_CODES + k3], 1);
}

__global__ void __launch_bounds__(256) count_tail_kernel(
    const int* __restrict__ x,
    const int* __restrict__ atom_idx,
    const int* __restrict__ cycle_idx,
    int start, int E)
{
    int e = start + blockIdx.x * blockDim.x + threadIdx.x;
    if (e >= E) return;
    int a = __ldg(&atom_idx[e]);
    int c = __ldg(&cycle_idx[e]);
    int code = __ldg(&x[a]);
    atomicAdd(&g_counts[c * NUM_CODES + code], 1);
}

__global__ void __launch_bounds__(ETHREADS, 3) expand_kernel(
    const float* __restrict__ emb,       // [22, 128]
    float* __restrict__ out,             // [S, 128]
    int S)
{
    __shared__ __half2 s_emb[NUM_CODES * HIDDEN / 2];     // 5.5 KB, fp16
    __shared__ int4    s_term4[EWARPS * NUM_CODES];       // 5.6 KB

    // stage emb -> fp16 smem
    {
        const float4* e4 = reinterpret_cast<const float4*>(emb);
        for (int i = threadIdx.x; i < NUM_CODES * HIDDEN / 4; i += ETHREADS) {
            float4 v = __ldg(e4 + i);
            s_emb[i * 2 + 0] = __floats2half2_rn(v.x, v.y);
            s_emb[i * 2 + 1] = __floats2half2_rn(v.z, v.w);
        }
    }

    const int lane = threadIdx.x & 31;
    const int warp = threadIdx.x >> 5;                    // 0..15
    const int row_base = blockIdx.x * ROWS_PER_BLOCK + warp * ROWS_PER_WARP;
    const unsigned FULL = 0xffffffffu;

    // ---- load counts for 4 rows (independent 88B loads) ----
    int cnt[ROWS_PER_WARP];
    #pragma unroll
    for (int r = 0; r < ROWS_PER_WARP; r++) {
        int row = row_base + r;
        cnt[r] = (lane < NUM_CODES && row < S)
                   ? __ldg(&g_counts[row * NUM_CODES + lane]) : 0;
    }

    // ---- build transposed term lists in smem ----
    // pack_r = ((code*256) << 16) | bf16bits((float)count)   (256 = fp16 row bytes)
    int pk[ROWS_PER_WARP];
    int m = 0;
    #pragma unroll
    for (int r = 0; r < ROWS_PER_WARP; r++) {
        unsigned mask = __ballot_sync(FULL, cnt[r] != 0);
        int nt = __popc(mask);
        m = max(m, nt);
        int code = (lane < nt) ? (__fns(mask, 0, lane + 1)) : 0;
        int c2 = __shfl_sync(FULL, cnt[r], code);
        unsigned bf = __float_as_uint((float)c2) >> 16;   // exact for small ints
        pk[r] = (lane < nt) ? (((code * (HIDDEN * 2)) << 16) | (int)bf) : 0;
        // zero-restore
        int row = row_base + r;
        if (lane < NUM_CODES && row < S)
            g_counts[row * NUM_CODES + lane] = 0;
    }
    if (lane < NUM_CODES)
        s_term4[warp * NUM_CODES + lane] = make_int4(pk[0], pk[1], pk[2], pk[3]);
    __syncthreads();   // s_emb + s_term4 ready

    // ---- hot loop: broadcast LDS.128 terms + 4x LDS.64 fp16 emb ----
    const char* const embb = (const char*)s_emb;
    const uint32_t lane_off = (uint32_t)lane << 3;        // lane*8 bytes
    const int4* tlist = &s_term4[warp * NUM_CODES];

    float4 acc0 = make_float4(0.f,0.f,0.f,0.f), acc1 = acc0, acc2 = acc0, acc3 = acc0;

    for (int j = 0; j < m; j++) {
        int4 t = tlist[j];                                // broadcast, 1 wavefront

        float f0 = __uint_as_float((unsigned)t.x << 16);
        float f1 = __uint_as_float((unsigned)t.y << 16);
        float f2 = __uint_as_float((unsigned)t.z << 16);
        float f3 = __uint_as_float((unsigned)t.w << 16);

        const __half2* p0 = reinterpret_cast<const __half2*>(embb + ((uint32_t)t.x >> 16) + lane_off);
        const __half2* p1 = reinterpret_cast<const __half2*>(embb + ((uint32_t)t.y >> 16) + lane_off);
        const __half2* p2 = reinterpret_cast<const __half2*>(embb + ((uint32_t)t.z >> 16) + lane_off);
        const __half2* p3 = reinterpret_cast<const __half2*>(embb + ((uint32_t)t.w >> 16) + lane_off);
        __half2 h0a = p0[0], h0b = p0[1];
        __half2 h1a = p1[0], h1b = p1[1];
        __half2 h2a = p2[0], h2b = p2[1];
        __half2 h3a = p3[0], h3b = p3[1];

        float2 a0 = __half22float2(h0a), b0 = __half22float2(h0b);
        float2 a1 = __half22float2(h1a), b1 = __half22float2(h1b);
        float2 a2 = __half22float2(h2a), b2 = __half22float2(h2b);
        float2 a3 = __half22float2(h3a), b3 = __half22float2(h3b);

        acc0.x += f0*a0.x; acc0.y += f0*a0.y; acc0.z += f0*b0.x; acc0.w += f0*b0.y;
        acc1.x += f1*a1.x; acc1.y += f1*a1.y; acc1.z += f1*b1.x; acc1.w += f1*b1.y;
        acc2.x += f2*a2.x; acc2.y += f2*a2.y; acc2.z += f2*b2.x; acc2.w += f2*b2.y;
        acc3.x += f3*a3.x; acc3.y += f3*a3.y; acc3.z += f3*b3.x; acc3.w += f3*b3.y;
    }

    float4* out4 = reinterpret_cast<float4*>(out);
    if (row_base + 0 < S) out4[(size_t)(row_base + 0) * 32 + lane] = acc0;
    if (row_base + 1 < S) out4[(size_t)(row_base + 1) * 32 + lane] = acc1;
    if (row_base + 2 < S) out4[(size_t)(row_base + 2) * 32 + lane] = acc2;
    if (row_base + 3 < S) out4[(size_t)(row_base + 3) * 32 + lane] = acc3;
}

extern "C" void kernel_launch(void* const* d_in, const int* in_sizes, int n_in,
                              void* d_out, int out_size)
{
    const int*   x   = (const int*)d_in[0];
    const int*   a2c = (const int*)d_in[1];
    const float* emb = (const float*)d_in[2];
    float*       out = (float*)d_out;

    const int E = in_sizes[1] / 2;                   // 600000
    const int S = out_size / HIDDEN;                 // 100000
    const int* atom_idx  = a2c;
    const int* cycle_idx = a2c + E;

    // 1) histogram edges into (cycle, code) counts, 4 edges/thread
    int E4 = E >> 2;
    if (E4 > 0)
        count_kernel<<<(E4 + 255) / 256, 256>>>(x, atom_idx, cycle_idx, E4);
    if (E & 3) {
        int start = E4 << 2, n = E - start;
        count_tail_kernel<<<(n + 255) / 256, 256>>>(x, atom_idx, cycle_idx, start, E);
    }

    // 2) expand counts -> output rows (64 rows/block); also re-zeros counts
    expand_kernel<<<(S + ROWS_PER_BLOCK - 1) / ROWS_PER_BLOCK, ETHREADS>>>(emb, out, S);
}